// round 11
// baseline (speedup 1.0000x reference)
#include <cuda_runtime.h>
#include <cuda_bf16.h>
#include <cuda_fp16.h>
#include <cstdint>

// ---------------------------------------------------------------------------
// Arch-path detection (arch-specific pass is live; tcgen05 runs there)
// ---------------------------------------------------------------------------
#if defined(__CUDA_ARCH_SPECIFIC__) || defined(__CUDA_ARCH_FAMILY_SPECIFIC__)
#define TCG_OK 1
#else
#define TCG_OK 0
#endif

#define T_DIM 8192
#define I_DIM 4096
#define O_DIM 4096

// Static scratch: fp16 x and fp16 dequantized W (single-pass precision plan)
__device__ __half g_Ah[(size_t)T_DIM * I_DIM];
__device__ __half g_Bh[(size_t)O_DIM * I_DIM];

// ---------------------------------------------------------------------------
// Portable helpers
// ---------------------------------------------------------------------------
__device__ __forceinline__ uint32_t smem_to_u32(const void* p) {
    uint32_t a;
    asm("{ .reg .u64 t; cvta.to.shared.u64 t, %1; cvt.u32.u64 %0, t; }" : "=r"(a) : "l"(p));
    return a;
}
__device__ __forceinline__ void cp_async16(uint32_t s, const void* g) {
    asm volatile("cp.async.cg.shared.global [%0], [%1], 16;" :: "r"(s), "l"(g) : "memory");
}
#define CP_COMMIT() asm volatile("cp.async.commit_group;" ::: "memory")
#define CP_WAIT_GROUP_2() asm volatile("cp.async.wait_group 2;" ::: "memory")
#define CP_WAIT_GROUP_3() asm volatile("cp.async.wait_group 3;" ::: "memory")
#define SMEM_SWIZZLE_128B(b) ((b) ^ (((b) >> 3) & 0x70))

__device__ __forceinline__ void ldsm_x4(uint32_t* r, uint32_t addr) {
    asm volatile("ldmatrix.sync.aligned.m8n8.x4.shared.b16 {%0,%1,%2,%3}, [%4];"
                 : "=r"(r[0]), "=r"(r[1]), "=r"(r[2]), "=r"(r[3]) : "r"(addr));
}
__device__ __forceinline__ void mma16816_f16(float* d, const uint32_t* a, const uint32_t* b) {
    asm volatile(
        "mma.sync.aligned.m16n8k16.row.col.f32.f16.f16.f32 "
        "{%0,%1,%2,%3}, {%4,%5,%6,%7}, {%8,%9}, {%0,%1,%2,%3};"
        : "+f"(d[0]), "+f"(d[1]), "+f"(d[2]), "+f"(d[3])
        : "r"(a[0]), "r"(a[1]), "r"(a[2]), "r"(a[3]), "r"(b[0]), "r"(b[1]));
}

// ---------------------------------------------------------------------------
// Exact NVFP4 quantization math (bit-identical to fp32 reference)
// ---------------------------------------------------------------------------
__device__ __forceinline__ float q_e4m3(float x) {
    float s = (x > 0.f) ? 1.f : ((x < 0.f) ? -1.f : 0.f);
    float ax = fminf(fabsf(x), 448.0f);
    int e = -6;
    if (ax > 0.f) { e = ilogbf(ax); if (e < -6) e = -6; if (e > 8) e = 8; }
    float step  = __int_as_float((e + 127) << 23);
    float rstep = __int_as_float((127 - e) << 23);
    return s * (rintf(ax * rstep * 8.0f) * 0.125f * step);
}
__device__ __forceinline__ float q_e2m1(float x) {
    float s = (x > 0.f) ? 1.f : ((x < 0.f) ? -1.f : 0.f);
    float ax = fminf(fabsf(x), 6.0f);
    int e = 0;
    if (ax > 0.f) { e = ilogbf(ax); if (e < 0) e = 0; if (e > 2) e = 2; }
    float step  = __int_as_float((e + 127) << 23);
    float rstep = __int_as_float((127 - e) << 23);
    return s * (rintf(ax * rstep * 2.0f) * 0.5f * step);
}

// ---------------------------------------------------------------------------
// Prep kernel 1: dequantize W -> fp16, vectorized x4
// ---------------------------------------------------------------------------
__global__ void dequant_weight_kernel(const float* __restrict__ w,
                                      const float* __restrict__ pba,
                                      const float* __restrict__ gam) {
    size_t q = (size_t)blockIdx.x * blockDim.x + threadIdx.x;
    if (q >= (size_t)O_DIM * I_DIM / 4) return;
    size_t idx = q * 4;
    size_t o = idx >> 12;
    int i = (int)(idx & (I_DIM - 1));

    float gscale = __fdiv_rn(__ldg(gam), 2688.0f);               // /(6*448)
    float bf     = __fdiv_rn(__ldg(pba + o * (I_DIM / 16) + (i >> 4)), 6.0f);
    float bs     = q_e4m3(__fdiv_rn(bf, gscale)) * gscale;

    float4 wv = *reinterpret_cast<const float4*>(w + idx);
    float win[4] = {wv.x, wv.y, wv.z, wv.w};
    uint32_t hp[2];
#pragma unroll
    for (int j = 0; j < 2; j++) {
        float wd0 = 0.f, wd1 = 0.f;
        if (bs > 0.0f) {
            wd0 = q_e2m1(__fdiv_rn(win[2 * j + 0], fmaxf(bs, 1e-30f))) * bs;
            wd1 = q_e2m1(__fdiv_rn(win[2 * j + 1], fmaxf(bs, 1e-30f))) * bs;
        }
        __half2 hh;
        hh.x = __float2half_rn(wd0);
        hh.y = __float2half_rn(wd1);
        hp[j] = *reinterpret_cast<uint32_t*>(&hh);
    }
    *reinterpret_cast<uint2*>(g_Bh + idx) = make_uint2(hp[0], hp[1]);
}

// ---------------------------------------------------------------------------
// Prep kernel 2: x -> fp16, vectorized x4
// ---------------------------------------------------------------------------
__global__ void split_x_kernel(const float* __restrict__ x) {
    size_t q = (size_t)blockIdx.x * blockDim.x + threadIdx.x;
    if (q >= (size_t)T_DIM * I_DIM / 4) return;
    size_t idx = q * 4;
    float4 v = *reinterpret_cast<const float4*>(x + idx);
    __half2 h0, h1;
    h0.x = __float2half_rn(v.x);
    h0.y = __float2half_rn(v.y);
    h1.x = __float2half_rn(v.z);
    h1.y = __float2half_rn(v.w);
    *reinterpret_cast<uint2*>(g_Ah + idx) =
        make_uint2(*reinterpret_cast<uint32_t*>(&h0), *reinterpret_cast<uint32_t*>(&h1));
}

// ===========================================================================
// PATH A: cg1 tcgen05 GEMM — M=256 x N=256 CTA tile (two M=128 accumulators),
// BK=64, 3-stage cp.async pipeline. 64 B of L2 ingest per MMA cycle (was 96).
// ===========================================================================
constexpr int BM = 256;
constexpr int BN = 256;
constexpr int BK = 64;
constexpr int NCH = I_DIM / BK;                // 64 chunks
constexpr int NSTG = 3;
constexpr int A_BYTES = BM * 128;              // 32 KB
constexpr int B_BYTES = BN * 128;              // 32 KB
constexpr int STG_BYTES = A_BYTES + B_BYTES;   // 64 KB
constexpr int SM_TMEMPTR = 0;
constexpr int SM_MBAR = 16;
constexpr int SM_TILES = 1024;
constexpr int SMEM_DYN = SM_TILES + NSTG * STG_BYTES;   // 197632 B

// idesc per MMA: D=F32, A=F16, B=F16, N=256, M=128
constexpr uint32_t IDESC =
    (1u << 4) | ((BN / 8) << 17) | ((128 / 16) << 24);

static constexpr uint64_t SMEM_DESC_BASE_SW128 =
    (uint64_t(2) << 61) | (uint64_t(1) << 46) | (uint64_t(64) << 32) | (uint64_t(1) << 16);
#define MAKE_SMEM_DESC(base_addr) \
    (SMEM_DESC_BASE_SW128 | ((uint64_t)((base_addr) >> 4) & 0x3FFF))

#if TCG_OK
__device__ __forceinline__ uint32_t elect_one_pred() {
    uint32_t pred;
    asm volatile(
        "{\n\t.reg .pred p;\n\telect.sync _|p, 0xFFFFFFFF;\n\tselp.b32 %0, 1, 0, p;\n\t}"
        : "=r"(pred));
    return pred;
}

#define MBARRIER_INIT(addr, count) \
    asm volatile("mbarrier.init.shared.b64 [%0], %1;" :: "r"((uint32_t)(addr)), "r"((uint32_t)(count)) : "memory")

#define MBARRIER_WAIT_PARITY(mbar_smem_addr, phase_parity) do { \
    uint32_t _mbar = (uint32_t)(mbar_smem_addr); \
    uint32_t _parity = (uint32_t)(phase_parity); \
    uint32_t _done; \
    asm volatile( \
        "{\n\t.reg .pred p;\n\t" \
        "mbarrier.try_wait.parity.acquire.cta.shared::cta.b64 p, [%1], %2;\n\t" \
        "selp.b32 %0, 1, 0, p;\n\t}" \
        : "=r"(_done) : "r"(_mbar), "r"(_parity) : "memory"); \
    if (!_done) { \
        asm volatile( \
            "{\n\t.reg .pred P1;\n\t" \
            "WAIT_LOOP_%=:\n\t" \
            "mbarrier.try_wait.parity.acquire.cta.shared::cta.b64 P1, [%0], %1, 0x989680;\n\t" \
            "@P1 bra.uni WAIT_DONE_%=;\n\t" \
            "bra.uni WAIT_LOOP_%=;\n\t" \
            "WAIT_DONE_%=:\n\t}" \
            :: "r"(_mbar), "r"(_parity) : "memory"); \
    } \
} while(0)

#define TCGEN05_ALLOC(smem_result_addr, nCols) \
    asm volatile("tcgen05.alloc.cta_group::1.sync.aligned.shared::cta.b32 [%0], %1;" \
        :: "r"((uint32_t)(smem_result_addr)), "r"((uint32_t)(nCols)) : "memory")
#define TCGEN05_DEALLOC(tmem_addr, nCols) \
    asm volatile("tcgen05.dealloc.cta_group::1.sync.aligned.b32 %0, %1;" \
        :: "r"(tmem_addr), "r"((uint32_t)(nCols)))
#define TCGEN05_RELINQUISH_ALLOC_PERMIT() \
    asm volatile("tcgen05.relinquish_alloc_permit.cta_group::1.sync.aligned;")
#define TCGEN05_COMMIT(mbar_smem_addr) \
    asm volatile("tcgen05.commit.cta_group::1.mbarrier::arrive::one.shared::cluster.b64 [%0];" \
        :: "r"((uint32_t)(mbar_smem_addr)) : "memory")
#define TCGEN05_WAIT_LD() asm volatile("tcgen05.wait::ld.sync.aligned;" ::: "memory")
#define TCGEN05_FENCE_AFTER() asm volatile("tcgen05.fence::after_thread_sync;" ::: "memory")
#define FENCE_PROXY_ASYNC_SHARED_CTA() asm volatile("fence.proxy.async.shared::cta;" ::: "memory")

#define TCGEN05_LD_32X32B_X32(r, tmem_addr) \
    asm volatile( \
        "tcgen05.ld.sync.aligned.32x32b.x32.b32 " \
        "{%0, %1, %2, %3, %4, %5, %6, %7, " \
        " %8, %9, %10, %11, %12, %13, %14, %15, " \
        " %16, %17, %18, %19, %20, %21, %22, %23, " \
        " %24, %25, %26, %27, %28, %29, %30, %31}, [%32];" \
        : "=r"((r)[0]),  "=r"((r)[1]),  "=r"((r)[2]),  "=r"((r)[3]), \
          "=r"((r)[4]),  "=r"((r)[5]),  "=r"((r)[6]),  "=r"((r)[7]), \
          "=r"((r)[8]),  "=r"((r)[9]),  "=r"((r)[10]), "=r"((r)[11]), \
          "=r"((r)[12]), "=r"((r)[13]), "=r"((r)[14]), "=r"((r)[15]), \
          "=r"((r)[16]), "=r"((r)[17]), "=r"((r)[18]), "=r"((r)[19]), \
          "=r"((r)[20]), "=r"((r)[21]), "=r"((r)[22]), "=r"((r)[23]), \
          "=r"((r)[24]), "=r"((r)[25]), "=r"((r)[26]), "=r"((r)[27]), \
          "=r"((r)[28]), "=r"((r)[29]), "=r"((r)[30]), "=r"((r)[31]) \
        : "r"(tmem_addr))

__device__ __forceinline__ void mma_f16_ss(uint32_t d, uint64_t ad, uint64_t bd,
                                           uint32_t idesc, bool acc) {
    uint32_t en = acc ? 1u : 0u;
    asm volatile(
        "{\n\t.reg .pred p;\n\tsetp.ne.u32 p, %5, 0;\n\t"
        "tcgen05.mma.cta_group::1.kind::f16 [%0], %1, %2, %3, {%4, %4, %4, %4}, p;\n\t}"
        :: "r"(d), "l"(ad), "l"(bd), "r"(idesc), "r"(0u), "r"(en)
        : "memory");
}
#endif  // TCG_OK

__global__ void __launch_bounds__(256, 1)
nvfp4_gemm_tcgen05(float* __restrict__ out) {
#if TCG_OK
    extern __shared__ char smem[];
    const uint32_t sb = smem_to_u32(smem);
    const int tid = threadIdx.x;
    const int wid = tid >> 5;
    const int lid = tid & 31;

    if (wid == 0) TCGEN05_ALLOC(sb + SM_TMEMPTR, 512);
    if (tid == 0) {
#pragma unroll
        for (int s = 0; s < NSTG; s++) MBARRIER_INIT(sb + SM_MBAR + 8 * s, 1);
    }
    __syncthreads();
    uint32_t tmem;
    asm volatile("ld.shared.b32 %0, [%1];" : "=r"(tmem) : "r"(sb + SM_TMEMPTR));

    const size_t m0 = (size_t)blockIdx.y * BM;
    const size_t n0 = (size_t)blockIdx.x * BN;

    // loader slots: 8 A + 8 B x 16B per thread (each tile 256 rows x 128B)
    uint32_t a_soff[8], b_soff[8];
    size_t a_goff[8], b_goff[8];
#pragma unroll
    for (int i = 0; i < 8; i++) {
        int idx = tid + i * 256;
        int r = idx >> 3, c16 = idx & 7;
        uint32_t sw = SMEM_SWIZZLE_128B((uint32_t)(r * 128 + c16 * 16));
        a_soff[i] = sw;
        b_soff[i] = (uint32_t)A_BYTES + sw;
        a_goff[i] = (m0 + r) * (size_t)I_DIM + (size_t)c16 * 8;
        b_goff[i] = (n0 + r) * (size_t)I_DIM + (size_t)c16 * 8;
    }

    auto load_chunk = [&](int c) {
        int s = c - (c / 3) * 3;                 // c % 3
        uint32_t base = sb + SM_TILES + s * STG_BYTES;
        size_t kk = (size_t)c * BK;
#pragma unroll
        for (int i = 0; i < 8; i++) cp_async16(base + a_soff[i], g_Ah + a_goff[i] + kk);
#pragma unroll
        for (int i = 0; i < 8; i++) cp_async16(base + b_soff[i], g_Bh + b_goff[i] + kk);
    };

    // prologue: stages 0,1
#pragma unroll 1
    for (int c = 0; c < NSTG - 1; c++) { load_chunk(c); CP_COMMIT(); }

    // mainloop
#pragma unroll 1
    for (int k = 0; k < NCH; k++) {
        int cl = k + NSTG - 1;
        if (cl < NCH) {
            if (cl >= NSTG) {
                // stage reuse: wait for MMA of chunk cl-3 (same stage, prev phase)
                int s = cl - (cl / 3) * 3;
                int par = ((cl / 3) - 1) & 1;
                MBARRIER_WAIT_PARITY(sb + SM_MBAR + 8 * s, par);
            }
            load_chunk(cl);
        }
        CP_COMMIT();
        CP_WAIT_GROUP_2();     // chunk k's cp.async retired (this thread)
        __syncthreads();       // ... for all threads
        if (wid == 0) {
            FENCE_PROXY_ASYNC_SHARED_CTA();
            if (elect_one_pred()) {
                int s = k - (k / 3) * 3;
                uint32_t base = sb + SM_TILES + s * STG_BYTES;
                uint64_t ad0 = MAKE_SMEM_DESC(base);
                uint64_t ad1 = MAKE_SMEM_DESC(base + A_BYTES / 2);  // rows 128..255
                uint64_t bd  = MAKE_SMEM_DESC(base + A_BYTES);
                bool first = (k == 0);
#pragma unroll
                for (int j = 0; j < 4; j++) {    // 4 x K=16 cover BK=64 (+2 = 32B)
                    mma_f16_ss(tmem,       ad0 + j * 2, bd + j * 2, IDESC, !(first && j == 0));
                    mma_f16_ss(tmem + 256, ad1 + j * 2, bd + j * 2, IDESC, !(first && j == 0));
                }
                TCGEN05_COMMIT(sb + SM_MBAR + 8 * s);
            }
        }
    }

    // wait for final chunk's MMA (commit tracks all prior MMAs)
    {
        int kl = NCH - 1;
        int s = kl - (kl / 3) * 3;
        int par = (kl / 3) & 1;
        MBARRIER_WAIT_PARITY(sb + SM_MBAR + 8 * s, par);
    }
    TCGEN05_FENCE_AFTER();

    // epilogue: accumulator h covers M rows [m0+h*128, +128); 256 fp32 cols each
    if (wid < 4) {
#pragma unroll 1
        for (int h = 0; h < 2; h++) {
            size_t row = m0 + (size_t)(h * 128) + (size_t)(wid * 32 + lid);
            float* op = out + row * (size_t)O_DIM + n0;
            uint32_t tb = tmem + (uint32_t)(h * 256);
#pragma unroll 1
            for (int cb = 0; cb < 8; cb++) {
                uint32_t r[32];
                TCGEN05_LD_32X32B_X32(r, tb + cb * 32);
                TCGEN05_WAIT_LD();
#pragma unroll
                for (int q = 0; q < 8; q++) {
                    float4 v;
                    v.x = __uint_as_float(r[q * 4 + 0]);
                    v.y = __uint_as_float(r[q * 4 + 1]);
                    v.z = __uint_as_float(r[q * 4 + 2]);
                    v.w = __uint_as_float(r[q * 4 + 3]);
                    *reinterpret_cast<float4*>(op + cb * 32 + q * 4) = v;
                }
            }
        }
    }

    __syncthreads();
    if (wid == 0) {
        TCGEN05_RELINQUISH_ALLOC_PERMIT();
        TCGEN05_DEALLOC(tmem, 512);
    }
#endif  // TCG_OK
}

// ===========================================================================
// PATH B: portable mma.sync fallback (fp16) — empty body in the live cubin
// ===========================================================================
constexpr int FBM = 128, FBN = 128, FBK = 64;
constexpr int FNCH = I_DIM / FBK;
constexpr int FSTG = 4;
constexpr int F_ABYTES = FBM * 128;
constexpr int F_STGB = F_ABYTES + FBN * 128;
constexpr int F_SMEM = FSTG * F_STGB;

__global__ void __launch_bounds__(256, 1)
nvfp4_gemm_mmasync(float* __restrict__ out) {
#if !TCG_OK
    extern __shared__ char smem[];
    const uint32_t sb = smem_to_u32(smem);
    const int tid = (int)threadIdx.x;
    const int wid = tid >> 5;
    const int lane = tid & 31;
    const int wm = wid & 1;
    const int wn = wid >> 1;

    const size_t m0 = (size_t)blockIdx.y * FBM;
    const size_t n0 = (size_t)blockIdx.x * FBN;

    uint32_t soff[8];
    size_t goff[8];
#pragma unroll
    for (int i = 0; i < 8; i++) {
        int idx = tid + i * 256;
        if (i < 4) {
            int r = idx >> 3, c16 = idx & 7;
            soff[i] = SMEM_SWIZZLE_128B((uint32_t)(r * 128 + c16 * 16));
            goff[i] = (m0 + r) * (size_t)I_DIM + (size_t)c16 * 8;
        } else {
            int idx2 = idx - 1024;
            int r = idx2 >> 3, c16 = idx2 & 7;
            soff[i] = (uint32_t)F_ABYTES + SMEM_SWIZZLE_128B((uint32_t)(r * 128 + c16 * 16));
            goff[i] = (n0 + r) * (size_t)I_DIM + (size_t)c16 * 8;
        }
    }

    auto load_chunk = [&](int c) {
        int s = c & (FSTG - 1);
        uint32_t base = sb + s * F_STGB;
        size_t kk = (size_t)c * FBK;
#pragma unroll
        for (int i = 0; i < 4; i++) cp_async16(base + soff[i], g_Ah + goff[i] + kk);
#pragma unroll
        for (int i = 4; i < 8; i++) cp_async16(base + soff[i], g_Bh + goff[i] + kk);
    };

    uint32_t arow128[4], axor[4];
    const uint32_t ahix = (uint32_t)((lane >> 4) * 16);
#pragma unroll
    for (int i = 0; i < 4; i++) {
        int row = wm * 64 + i * 16 + (lane & 7) + ((lane >> 3) & 1) * 8;
        arow128[i] = (uint32_t)(row * 128);
        axor[i] = (uint32_t)((row & 7) << 4);
    }
    uint32_t brow128[2], bxor[2];
    const uint32_t bhix = (uint32_t)(((lane >> 3) & 1) * 16);
#pragma unroll
    for (int jj = 0; jj < 2; jj++) {
        int row = wn * 32 + jj * 16 + (lane & 7) + ((lane >> 4) & 1) * 8;
        brow128[jj] = (uint32_t)(row * 128);
        bxor[jj] = (uint32_t)((row & 7) << 4);
    }

    float c[4][4][4];
#pragma unroll
    for (int i = 0; i < 4; i++)
#pragma unroll
        for (int j = 0; j < 4; j++)
#pragma unroll
            for (int r = 0; r < 4; r++) c[i][j][r] = 0.0f;

#pragma unroll 1
    for (int cch = 0; cch < FSTG; cch++) { load_chunk(cch); CP_COMMIT(); }

#pragma unroll 1
    for (int k = 0; k < FNCH; k++) {
        CP_WAIT_GROUP_3();
        __syncthreads();
        uint32_t Abase = sb + (uint32_t)((k & (FSTG - 1)) * F_STGB);
        uint32_t Bbase = Abase + F_ABYTES;
#pragma unroll
        for (int q = 0; q < 4; q++) {
            uint32_t qa = (uint32_t)(q * 32) + ahix;
            uint32_t qb = (uint32_t)(q * 32) + bhix;
            uint32_t a[4][4], b[2][4];
#pragma unroll
            for (int i = 0; i < 4; i++)
                ldsm_x4(a[i], Abase + arow128[i] + (qa ^ axor[i]));
#pragma unroll
            for (int jj = 0; jj < 2; jj++)
                ldsm_x4(b[jj], Bbase + brow128[jj] + (qb ^ bxor[jj]));
#pragma unroll
            for (int i = 0; i < 4; i++)
#pragma unroll
                for (int jj = 0; jj < 2; jj++) {
                    mma16816_f16(c[i][2 * jj + 0], a[i], &b[jj][0]);
                    mma16816_f16(c[i][2 * jj + 1], a[i], &b[jj][2]);
                }
        }
        __syncthreads();
        if (k + FSTG < FNCH) load_chunk(k + FSTG);
        CP_COMMIT();
    }

    const size_t rbase = m0 + (size_t)(wm * 64) + (size_t)(lane >> 2);
    const size_t cbase = n0 + (size_t)(wn * 32) + (size_t)((lane & 3) * 2);
#pragma unroll
    for (int i = 0; i < 4; i++)
#pragma unroll
        for (int j = 0; j < 4; j++) {
            size_t row = rbase + (size_t)(i * 16);
            size_t col = cbase + (size_t)(j * 8);
            *reinterpret_cast<float2*>(out + row * O_DIM + col) =
                make_float2(c[i][j][0], c[i][j][1]);
            *reinterpret_cast<float2*>(out + (row + 8) * O_DIM + col) =
                make_float2(c[i][j][2], c[i][j][3]);
        }
#endif  // !TCG_OK
}

// ---------------------------------------------------------------------------
// Launch
// ---------------------------------------------------------------------------
extern "C" void kernel_launch(void* const* d_in, const int* in_sizes, int n_in,
                              void* d_out, int out_size) {
    const float* x   = (const float*)d_in[0];
    const float* w   = (const float*)d_in[1];
    const float* pba = (const float*)d_in[2];
    const float* gam = (const float*)d_in[3];
    float* out = (float*)d_out;

    cudaFuncSetAttribute(nvfp4_gemm_tcgen05,
                         cudaFuncAttributeMaxDynamicSharedMemorySize, SMEM_DYN);
    cudaFuncSetAttribute(nvfp4_gemm_mmasync,
                         cudaFuncAttributeMaxDynamicSharedMemorySize, F_SMEM);

    {
        size_t n = (size_t)O_DIM * I_DIM / 4;
        dequant_weight_kernel<<<(unsigned)((n + 255) / 256), 256>>>(w, pba, gam);
    }
    {
        size_t n = (size_t)T_DIM * I_DIM / 4;
        split_x_kernel<<<(unsigned)((n + 255) / 256), 256>>>(x);
    }
    {
        dim3 grid(O_DIM / BN, T_DIM / BM, 1);   // (16, 32) = 512 CTAs
        nvfp4_gemm_tcgen05<<<grid, 256, SMEM_DYN>>>(out);
    }
    {
        dim3 grid(O_DIM / FBN, T_DIM / FBM, 1); // fallback (empty in live cubin)
        nvfp4_gemm_mmasync<<<grid, 256, F_SMEM>>>(out);
    }
}

// round 12
// speedup vs baseline: 1.0026x; 1.0026x over previous
#include <cuda_runtime.h>
#include <cuda_bf16.h>
#include <cuda_fp16.h>
#include <cstdint>

// ---------------------------------------------------------------------------
// Arch-path detection (arch-specific pass is live; tcgen05 runs there)
// ---------------------------------------------------------------------------
#if defined(__CUDA_ARCH_SPECIFIC__) || defined(__CUDA_ARCH_FAMILY_SPECIFIC__)
#define TCG_OK 1
#else
#define TCG_OK 0
#endif

#define T_DIM 8192
#define I_DIM 4096
#define O_DIM 4096

// Static scratch: fp16 x and fp16 dequantized W (single-pass precision plan)
__device__ __half g_Ah[(size_t)T_DIM * I_DIM];
__device__ __half g_Bh[(size_t)O_DIM * I_DIM];

// ---------------------------------------------------------------------------
// Portable helpers
// ---------------------------------------------------------------------------
__device__ __forceinline__ uint32_t smem_to_u32(const void* p) {
    uint32_t a;
    asm("{ .reg .u64 t; cvta.to.shared.u64 t, %1; cvt.u32.u64 %0, t; }" : "=r"(a) : "l"(p));
    return a;
}
__device__ __forceinline__ void cp_async16(uint32_t s, const void* g) {
    asm volatile("cp.async.cg.shared.global [%0], [%1], 16;" :: "r"(s), "l"(g) : "memory");
}
#define CP_COMMIT() asm volatile("cp.async.commit_group;" ::: "memory")
#define CP_WAIT_GROUP_3() asm volatile("cp.async.wait_group 3;" ::: "memory")
#define SMEM_SWIZZLE_128B(b) ((b) ^ (((b) >> 3) & 0x70))

__device__ __forceinline__ void ldsm_x4(uint32_t* r, uint32_t addr) {
    asm volatile("ldmatrix.sync.aligned.m8n8.x4.shared.b16 {%0,%1,%2,%3}, [%4];"
                 : "=r"(r[0]), "=r"(r[1]), "=r"(r[2]), "=r"(r[3]) : "r"(addr));
}
__device__ __forceinline__ void mma16816_f16(float* d, const uint32_t* a, const uint32_t* b) {
    asm volatile(
        "mma.sync.aligned.m16n8k16.row.col.f32.f16.f16.f32 "
        "{%0,%1,%2,%3}, {%4,%5,%6,%7}, {%8,%9}, {%0,%1,%2,%3};"
        : "+f"(d[0]), "+f"(d[1]), "+f"(d[2]), "+f"(d[3])
        : "r"(a[0]), "r"(a[1]), "r"(a[2]), "r"(a[3]), "r"(b[0]), "r"(b[1]));
}

// ---------------------------------------------------------------------------
// Exact NVFP4 quantization math (bit-identical to fp32 reference)
// ---------------------------------------------------------------------------
__device__ __forceinline__ float q_e4m3(float x) {
    float s = (x > 0.f) ? 1.f : ((x < 0.f) ? -1.f : 0.f);
    float ax = fminf(fabsf(x), 448.0f);
    int e = -6;
    if (ax > 0.f) { e = ilogbf(ax); if (e < -6) e = -6; if (e > 8) e = 8; }
    float step  = __int_as_float((e + 127) << 23);
    float rstep = __int_as_float((127 - e) << 23);
    return s * (rintf(ax * rstep * 8.0f) * 0.125f * step);
}
__device__ __forceinline__ float q_e2m1(float x) {
    float s = (x > 0.f) ? 1.f : ((x < 0.f) ? -1.f : 0.f);
    float ax = fminf(fabsf(x), 6.0f);
    int e = 0;
    if (ax > 0.f) { e = ilogbf(ax); if (e < 0) e = 0; if (e > 2) e = 2; }
    float step  = __int_as_float((e + 127) << 23);
    float rstep = __int_as_float((127 - e) << 23);
    return s * (rintf(ax * rstep * 2.0f) * 0.5f * step);
}

// ---------------------------------------------------------------------------
// Prep kernel 1: dequantize W -> fp16, vectorized x4
// ---------------------------------------------------------------------------
__global__ void dequant_weight_kernel(const float* __restrict__ w,
                                      const float* __restrict__ pba,
                                      const float* __restrict__ gam) {
    size_t q = (size_t)blockIdx.x * blockDim.x + threadIdx.x;
    if (q >= (size_t)O_DIM * I_DIM / 4) return;
    size_t idx = q * 4;
    size_t o = idx >> 12;
    int i = (int)(idx & (I_DIM - 1));

    float gscale = __fdiv_rn(__ldg(gam), 2688.0f);               // /(6*448)
    float bf     = __fdiv_rn(__ldg(pba + o * (I_DIM / 16) + (i >> 4)), 6.0f);
    float bs     = q_e4m3(__fdiv_rn(bf, gscale)) * gscale;

    float4 wv = *reinterpret_cast<const float4*>(w + idx);
    float win[4] = {wv.x, wv.y, wv.z, wv.w};
    uint32_t hp[2];
#pragma unroll
    for (int j = 0; j < 2; j++) {
        float wd0 = 0.f, wd1 = 0.f;
        if (bs > 0.0f) {
            wd0 = q_e2m1(__fdiv_rn(win[2 * j + 0], fmaxf(bs, 1e-30f))) * bs;
            wd1 = q_e2m1(__fdiv_rn(win[2 * j + 1], fmaxf(bs, 1e-30f))) * bs;
        }
        __half2 hh;
        hh.x = __float2half_rn(wd0);
        hh.y = __float2half_rn(wd1);
        hp[j] = *reinterpret_cast<uint32_t*>(&hh);
    }
    *reinterpret_cast<uint2*>(g_Bh + idx) = make_uint2(hp[0], hp[1]);
}

// ---------------------------------------------------------------------------
// Prep kernel 2: x -> fp16, vectorized x4
// ---------------------------------------------------------------------------
__global__ void split_x_kernel(const float* __restrict__ x) {
    size_t q = (size_t)blockIdx.x * blockDim.x + threadIdx.x;
    if (q >= (size_t)T_DIM * I_DIM / 4) return;
    size_t idx = q * 4;
    float4 v = *reinterpret_cast<const float4*>(x + idx);
    __half2 h0, h1;
    h0.x = __float2half_rn(v.x);
    h0.y = __float2half_rn(v.y);
    h1.x = __float2half_rn(v.z);
    h1.y = __float2half_rn(v.w);
    *reinterpret_cast<uint2*>(g_Ah + idx) =
        make_uint2(*reinterpret_cast<uint32_t*>(&h0), *reinterpret_cast<uint32_t*>(&h1));
}

// ===========================================================================
// PATH A: cg1 tcgen05 GEMM — M=256 x N=256 tile, warp-specialized
// producer/consumer: 256 loader threads + 1 MMA warp, mbarrier-ringed
// 3-stage pipeline, NO __syncthreads in the mainloop. Fetch || MMA.
// ===========================================================================
constexpr int BM = 256;
constexpr int BN = 256;
constexpr int BK = 64;
constexpr int NCH = I_DIM / BK;                // 64 chunks
constexpr int NSTG = 3;
constexpr int A_BYTES = BM * 128;              // 32 KB
constexpr int B_BYTES = BN * 128;              // 32 KB
constexpr int STG_BYTES = A_BYTES + B_BYTES;   // 64 KB
constexpr int SM_TMEMPTR = 0;
constexpr int SM_FULL = 16;                    // 3 x 8B, count=256 (producers)
constexpr int SM_DONE = 48;                    // 3 x 8B, count=1   (commit)
constexpr int SM_TILES = 1024;
constexpr int SMEM_DYN = SM_TILES + NSTG * STG_BYTES;   // 197632 B
constexpr int GEMM_THREADS = 288;              // 256 producers + MMA warp (wid 8)

// idesc per MMA: D=F32, A=F16, B=F16, N=256, M=128
constexpr uint32_t IDESC =
    (1u << 4) | ((BN / 8) << 17) | ((128 / 16) << 24);

static constexpr uint64_t SMEM_DESC_BASE_SW128 =
    (uint64_t(2) << 61) | (uint64_t(1) << 46) | (uint64_t(64) << 32) | (uint64_t(1) << 16);
#define MAKE_SMEM_DESC(base_addr) \
    (SMEM_DESC_BASE_SW128 | ((uint64_t)((base_addr) >> 4) & 0x3FFF))

#if TCG_OK
__device__ __forceinline__ uint32_t elect_one_pred() {
    uint32_t pred;
    asm volatile(
        "{\n\t.reg .pred p;\n\telect.sync _|p, 0xFFFFFFFF;\n\tselp.b32 %0, 1, 0, p;\n\t}"
        : "=r"(pred));
    return pred;
}

#define MBARRIER_INIT(addr, count) \
    asm volatile("mbarrier.init.shared.b64 [%0], %1;" :: "r"((uint32_t)(addr)), "r"((uint32_t)(count)) : "memory")

#define MBARRIER_WAIT_PARITY(mbar_smem_addr, phase_parity) do { \
    uint32_t _mbar = (uint32_t)(mbar_smem_addr); \
    uint32_t _parity = (uint32_t)(phase_parity); \
    uint32_t _done; \
    asm volatile( \
        "{\n\t.reg .pred p;\n\t" \
        "mbarrier.try_wait.parity.acquire.cta.shared::cta.b64 p, [%1], %2;\n\t" \
        "selp.b32 %0, 1, 0, p;\n\t}" \
        : "=r"(_done) : "r"(_mbar), "r"(_parity) : "memory"); \
    if (!_done) { \
        asm volatile( \
            "{\n\t.reg .pred P1;\n\t" \
            "WAIT_LOOP_%=:\n\t" \
            "mbarrier.try_wait.parity.acquire.cta.shared::cta.b64 P1, [%0], %1, 0x989680;\n\t" \
            "@P1 bra.uni WAIT_DONE_%=;\n\t" \
            "bra.uni WAIT_LOOP_%=;\n\t" \
            "WAIT_DONE_%=:\n\t}" \
            :: "r"(_mbar), "r"(_parity) : "memory"); \
    } \
} while(0)

// Arrive on mbarrier when all prior cp.async of THIS thread have completed.
// .noinc: expected count pre-accounted at init (count = 256 producers).
#define CP_ASYNC_MBAR_ARRIVE(addr) \
    asm volatile("cp.async.mbarrier.arrive.noinc.shared::cta.b64 [%0];" \
        :: "r"((uint32_t)(addr)) : "memory")

#define TCGEN05_ALLOC(smem_result_addr, nCols) \
    asm volatile("tcgen05.alloc.cta_group::1.sync.aligned.shared::cta.b32 [%0], %1;" \
        :: "r"((uint32_t)(smem_result_addr)), "r"((uint32_t)(nCols)) : "memory")
#define TCGEN05_DEALLOC(tmem_addr, nCols) \
    asm volatile("tcgen05.dealloc.cta_group::1.sync.aligned.b32 %0, %1;" \
        :: "r"(tmem_addr), "r"((uint32_t)(nCols)))
#define TCGEN05_RELINQUISH_ALLOC_PERMIT() \
    asm volatile("tcgen05.relinquish_alloc_permit.cta_group::1.sync.aligned;")
#define TCGEN05_COMMIT(mbar_smem_addr) \
    asm volatile("tcgen05.commit.cta_group::1.mbarrier::arrive::one.shared::cluster.b64 [%0];" \
        :: "r"((uint32_t)(mbar_smem_addr)) : "memory")
#define TCGEN05_WAIT_LD() asm volatile("tcgen05.wait::ld.sync.aligned;" ::: "memory")
#define TCGEN05_FENCE_AFTER() asm volatile("tcgen05.fence::after_thread_sync;" ::: "memory")
#define FENCE_PROXY_ASYNC_SHARED_CTA() asm volatile("fence.proxy.async.shared::cta;" ::: "memory")

#define TCGEN05_LD_32X32B_X32(r, tmem_addr) \
    asm volatile( \
        "tcgen05.ld.sync.aligned.32x32b.x32.b32 " \
        "{%0, %1, %2, %3, %4, %5, %6, %7, " \
        " %8, %9, %10, %11, %12, %13, %14, %15, " \
        " %16, %17, %18, %19, %20, %21, %22, %23, " \
        " %24, %25, %26, %27, %28, %29, %30, %31}, [%32];" \
        : "=r"((r)[0]),  "=r"((r)[1]),  "=r"((r)[2]),  "=r"((r)[3]), \
          "=r"((r)[4]),  "=r"((r)[5]),  "=r"((r)[6]),  "=r"((r)[7]), \
          "=r"((r)[8]),  "=r"((r)[9]),  "=r"((r)[10]), "=r"((r)[11]), \
          "=r"((r)[12]), "=r"((r)[13]), "=r"((r)[14]), "=r"((r)[15]), \
          "=r"((r)[16]), "=r"((r)[17]), "=r"((r)[18]), "=r"((r)[19]), \
          "=r"((r)[20]), "=r"((r)[21]), "=r"((r)[22]), "=r"((r)[23]), \
          "=r"((r)[24]), "=r"((r)[25]), "=r"((r)[26]), "=r"((r)[27]), \
          "=r"((r)[28]), "=r"((r)[29]), "=r"((r)[30]), "=r"((r)[31]) \
        : "r"(tmem_addr))

__device__ __forceinline__ void mma_f16_ss(uint32_t d, uint64_t ad, uint64_t bd,
                                           uint32_t idesc, bool acc) {
    uint32_t en = acc ? 1u : 0u;
    asm volatile(
        "{\n\t.reg .pred p;\n\tsetp.ne.u32 p, %5, 0;\n\t"
        "tcgen05.mma.cta_group::1.kind::f16 [%0], %1, %2, %3, {%4, %4, %4, %4}, p;\n\t}"
        :: "r"(d), "l"(ad), "l"(bd), "r"(idesc), "r"(0u), "r"(en)
        : "memory");
}
#endif  // TCG_OK

__global__ void __launch_bounds__(GEMM_THREADS, 1)
nvfp4_gemm_tcgen05(float* __restrict__ out) {
#if TCG_OK
    extern __shared__ char smem[];
    const uint32_t sb = smem_to_u32(smem);
    const int tid = (int)threadIdx.x;
    const int wid = tid >> 5;
    const int lid = tid & 31;

    if (wid == 0) TCGEN05_ALLOC(sb + SM_TMEMPTR, 512);
    if (tid == 0) {
#pragma unroll
        for (int s = 0; s < NSTG; s++) {
            MBARRIER_INIT(sb + SM_FULL + 8 * s, 256);  // one arrive per producer
            MBARRIER_INIT(sb + SM_DONE + 8 * s, 1);    // tcgen05.commit arrival
        }
    }
    __syncthreads();
    uint32_t tmem;
    asm volatile("ld.shared.b32 %0, [%1];" : "=r"(tmem) : "r"(sb + SM_TMEMPTR));

    const size_t m0 = (size_t)blockIdx.y * BM;
    const size_t n0 = (size_t)blockIdx.x * BN;

    // ---------------- producers: tids 0..255 ----------------
    if (tid < 256) {
        uint32_t a_soff[8], b_soff[8];
        size_t a_goff[8], b_goff[8];
#pragma unroll
        for (int i = 0; i < 8; i++) {
            int idx = tid + i * 256;
            int r = idx >> 3, c16 = idx & 7;
            uint32_t sw = SMEM_SWIZZLE_128B((uint32_t)(r * 128 + c16 * 16));
            a_soff[i] = sw;
            b_soff[i] = (uint32_t)A_BYTES + sw;
            a_goff[i] = (m0 + r) * (size_t)I_DIM + (size_t)c16 * 8;
            b_goff[i] = (n0 + r) * (size_t)I_DIM + (size_t)c16 * 8;
        }
#pragma unroll 1
        for (int c = 0; c < NCH; c++) {
            int s = c - (c / 3) * 3;                       // c % 3
            if (c >= NSTG)                                 // stage reuse gate
                MBARRIER_WAIT_PARITY(sb + SM_DONE + 8 * s, ((c / 3) - 1) & 1);
            uint32_t base = sb + SM_TILES + s * STG_BYTES;
            size_t kk = (size_t)c * BK;
#pragma unroll
            for (int i = 0; i < 8; i++) cp_async16(base + a_soff[i], g_Ah + a_goff[i] + kk);
#pragma unroll
            for (int i = 0; i < 8; i++) cp_async16(base + b_soff[i], g_Bh + b_goff[i] + kk);
            CP_ASYNC_MBAR_ARRIVE(sb + SM_FULL + 8 * s);
        }
    }

    // ---------------- MMA issuer: warp 8, one elected lane ----------------
    if (wid == 8) {
        if (elect_one_pred()) {
#pragma unroll 1
            for (int k = 0; k < NCH; k++) {
                int s = k - (k / 3) * 3;
                MBARRIER_WAIT_PARITY(sb + SM_FULL + 8 * s, (k / 3) & 1);
                FENCE_PROXY_ASYNC_SHARED_CTA();
                uint32_t base = sb + SM_TILES + s * STG_BYTES;
                uint64_t ad0 = MAKE_SMEM_DESC(base);
                uint64_t ad1 = MAKE_SMEM_DESC(base + A_BYTES / 2);  // M rows 128..255
                uint64_t bd  = MAKE_SMEM_DESC(base + A_BYTES);
                bool first = (k == 0);
#pragma unroll
                for (int j = 0; j < 4; j++) {    // 4 x K=16 cover BK=64 (+2 = 32B)
                    mma_f16_ss(tmem,       ad0 + j * 2, bd + j * 2, IDESC, !(first && j == 0));
                    mma_f16_ss(tmem + 256, ad1 + j * 2, bd + j * 2, IDESC, !(first && j == 0));
                }
                TCGEN05_COMMIT(sb + SM_DONE + 8 * s);
            }
        }
    }

    // ---------------- epilogue: wait final chunk's MMA, drain TMEM ----------
    {
        int kl = NCH - 1;
        int s = kl - (kl / 3) * 3;
        MBARRIER_WAIT_PARITY(sb + SM_DONE + 8 * s, (kl / 3) & 1);
    }
    TCGEN05_FENCE_AFTER();

    // warps 0-3 -> accumulator 0 (tile rows 0..127); warps 4-7 -> accumulator 1
    if (wid < 8) {
        int h = wid >> 2;
        size_t row = m0 + (size_t)(h * 128) + (size_t)((wid & 3) * 32 + lid);
        float* op = out + row * (size_t)O_DIM + n0;
        uint32_t tb = tmem + (uint32_t)(h * 256);
#pragma unroll 1
        for (int cb = 0; cb < 8; cb++) {
            uint32_t r[32];
            TCGEN05_LD_32X32B_X32(r, tb + cb * 32);
            TCGEN05_WAIT_LD();
#pragma unroll
            for (int q = 0; q < 8; q++) {
                float4 v;
                v.x = __uint_as_float(r[q * 4 + 0]);
                v.y = __uint_as_float(r[q * 4 + 1]);
                v.z = __uint_as_float(r[q * 4 + 2]);
                v.w = __uint_as_float(r[q * 4 + 3]);
                *reinterpret_cast<float4*>(op + cb * 32 + q * 4) = v;
            }
        }
    }

    __syncthreads();
    if (wid == 0) {
        TCGEN05_RELINQUISH_ALLOC_PERMIT();
        TCGEN05_DEALLOC(tmem, 512);
    }
#endif  // TCG_OK
}

// ===========================================================================
// PATH B: portable mma.sync fallback (fp16) — empty body in the live cubin
// ===========================================================================
constexpr int FBM = 128, FBN = 128, FBK = 64;
constexpr int FNCH = I_DIM / FBK;
constexpr int FSTG = 4;
constexpr int F_ABYTES = FBM * 128;
constexpr int F_STGB = F_ABYTES + FBN * 128;
constexpr int F_SMEM = FSTG * F_STGB;

__global__ void __launch_bounds__(256, 1)
nvfp4_gemm_mmasync(float* __restrict__ out) {
#if !TCG_OK
    extern __shared__ char smem[];
    const uint32_t sb = smem_to_u32(smem);
    const int tid = (int)threadIdx.x;
    const int wid = tid >> 5;
    const int lane = tid & 31;
    const int wm = wid & 1;
    const int wn = wid >> 1;

    const size_t m0 = (size_t)blockIdx.y * FBM;
    const size_t n0 = (size_t)blockIdx.x * FBN;

    uint32_t soff[8];
    size_t goff[8];
#pragma unroll
    for (int i = 0; i < 8; i++) {
        int idx = tid + i * 256;
        if (i < 4) {
            int r = idx >> 3, c16 = idx & 7;
            soff[i] = SMEM_SWIZZLE_128B((uint32_t)(r * 128 + c16 * 16));
            goff[i] = (m0 + r) * (size_t)I_DIM + (size_t)c16 * 8;
        } else {
            int idx2 = idx - 1024;
            int r = idx2 >> 3, c16 = idx2 & 7;
            soff[i] = (uint32_t)F_ABYTES + SMEM_SWIZZLE_128B((uint32_t)(r * 128 + c16 * 16));
            goff[i] = (n0 + r) * (size_t)I_DIM + (size_t)c16 * 8;
        }
    }

    auto load_chunk = [&](int c) {
        int s = c & (FSTG - 1);
        uint32_t base = sb + s * F_STGB;
        size_t kk = (size_t)c * FBK;
#pragma unroll
        for (int i = 0; i < 4; i++) cp_async16(base + soff[i], g_Ah + goff[i] + kk);
#pragma unroll
        for (int i = 4; i < 8; i++) cp_async16(base + soff[i], g_Bh + goff[i] + kk);
    };

    uint32_t arow128[4], axor[4];
    const uint32_t ahix = (uint32_t)((lane >> 4) * 16);
#pragma unroll
    for (int i = 0; i < 4; i++) {
        int row = wm * 64 + i * 16 + (lane & 7) + ((lane >> 3) & 1) * 8;
        arow128[i] = (uint32_t)(row * 128);
        axor[i] = (uint32_t)((row & 7) << 4);
    }
    uint32_t brow128[2], bxor[2];
    const uint32_t bhix = (uint32_t)(((lane >> 3) & 1) * 16);
#pragma unroll
    for (int jj = 0; jj < 2; jj++) {
        int row = wn * 32 + jj * 16 + (lane & 7) + ((lane >> 4) & 1) * 8;
        brow128[jj] = (uint32_t)(row * 128);
        bxor[jj] = (uint32_t)((row & 7) << 4);
    }

    float c[4][4][4];
#pragma unroll
    for (int i = 0; i < 4; i++)
#pragma unroll
        for (int j = 0; j < 4; j++)
#pragma unroll
            for (int r = 0; r < 4; r++) c[i][j][r] = 0.0f;

#pragma unroll 1
    for (int cch = 0; cch < FSTG; cch++) { load_chunk(cch); CP_COMMIT(); }

#pragma unroll 1
    for (int k = 0; k < FNCH; k++) {
        CP_WAIT_GROUP_3();
        __syncthreads();
        uint32_t Abase = sb + (uint32_t)((k & (FSTG - 1)) * F_STGB);
        uint32_t Bbase = Abase + F_ABYTES;
#pragma unroll
        for (int q = 0; q < 4; q++) {
            uint32_t qa = (uint32_t)(q * 32) + ahix;
            uint32_t qb = (uint32_t)(q * 32) + bhix;
            uint32_t a[4][4], b[2][4];
#pragma unroll
            for (int i = 0; i < 4; i++)
                ldsm_x4(a[i], Abase + arow128[i] + (qa ^ axor[i]));
#pragma unroll
            for (int jj = 0; jj < 2; jj++)
                ldsm_x4(b[jj], Bbase + brow128[jj] + (qb ^ bxor[jj]));
#pragma unroll
            for (int i = 0; i < 4; i++)
#pragma unroll
                for (int jj = 0; jj < 2; jj++) {
                    mma16816_f16(c[i][2 * jj + 0], a[i], &b[jj][0]);
                    mma16816_f16(c[i][2 * jj + 1], a[i], &b[jj][2]);
                }
        }
        __syncthreads();
        if (k + FSTG < FNCH) load_chunk(k + FSTG);
        CP_COMMIT();
    }

    const size_t rbase = m0 + (size_t)(wm * 64) + (size_t)(lane >> 2);
    const size_t cbase = n0 + (size_t)(wn * 32) + (size_t)((lane & 3) * 2);
#pragma unroll
    for (int i = 0; i < 4; i++)
#pragma unroll
        for (int j = 0; j < 4; j++) {
            size_t row = rbase + (size_t)(i * 16);
            size_t col = cbase + (size_t)(j * 8);
            *reinterpret_cast<float2*>(out + row * O_DIM + col) =
                make_float2(c[i][j][0], c[i][j][1]);
            *reinterpret_cast<float2*>(out + (row + 8) * O_DIM + col) =
                make_float2(c[i][j][2], c[i][j][3]);
        }
#endif  // !TCG_OK
}

// ---------------------------------------------------------------------------
// Launch
// ---------------------------------------------------------------------------
extern "C" void kernel_launch(void* const* d_in, const int* in_sizes, int n_in,
                              void* d_out, int out_size) {
    const float* x   = (const float*)d_in[0];
    const float* w   = (const float*)d_in[1];
    const float* pba = (const float*)d_in[2];
    const float* gam = (const float*)d_in[3];
    float* out = (float*)d_out;

    cudaFuncSetAttribute(nvfp4_gemm_tcgen05,
                         cudaFuncAttributeMaxDynamicSharedMemorySize, SMEM_DYN);
    cudaFuncSetAttribute(nvfp4_gemm_mmasync,
                         cudaFuncAttributeMaxDynamicSharedMemorySize, F_SMEM);

    {
        size_t n = (size_t)O_DIM * I_DIM / 4;
        dequant_weight_kernel<<<(unsigned)((n + 255) / 256), 256>>>(w, pba, gam);
    }
    {
        size_t n = (size_t)T_DIM * I_DIM / 4;
        split_x_kernel<<<(unsigned)((n + 255) / 256), 256>>>(x);
    }
    {
        dim3 grid(O_DIM / BN, T_DIM / BM, 1);   // (16, 32) = 512 CTAs
        nvfp4_gemm_tcgen05<<<grid, GEMM_THREADS, SMEM_DYN>>>(out);
    }
    {
        dim3 grid(O_DIM / FBN, T_DIM / FBM, 1); // fallback (empty in live cubin)
        nvfp4_gemm_mmasync<<<grid, 256, F_SMEM>>>(out);
    }
}

// round 14
// speedup vs baseline: 1.4502x; 1.4465x over previous
#include <cuda_runtime.h>
#include <cuda_bf16.h>
#include <cuda_fp16.h>
#include <cstdint>

// ---------------------------------------------------------------------------
// Arch-path detection (arch-specific pass is live; tcgen05 runs there)
// ---------------------------------------------------------------------------
#if defined(__CUDA_ARCH_SPECIFIC__) || defined(__CUDA_ARCH_FAMILY_SPECIFIC__)
#define TCG_OK 1
#else
#define TCG_OK 0
#endif

#define T_DIM 8192
#define I_DIM 4096
#define O_DIM 4096

// Static scratch: fp16 x and fp16 dequantized W (single-pass precision plan)
__device__ __half g_Ah[(size_t)T_DIM * I_DIM];
__device__ __half g_Bh[(size_t)O_DIM * I_DIM];

// ---------------------------------------------------------------------------
// Portable helpers
// ---------------------------------------------------------------------------
__device__ __forceinline__ uint32_t smem_to_u32(const void* p) {
    uint32_t a;
    asm("{ .reg .u64 t; cvta.to.shared.u64 t, %1; cvt.u32.u64 %0, t; }" : "=r"(a) : "l"(p));
    return a;
}
__device__ __forceinline__ void cp_async16(uint32_t s, const void* g) {
    asm volatile("cp.async.cg.shared.global [%0], [%1], 16;" :: "r"(s), "l"(g) : "memory");
}
#define CP_COMMIT() asm volatile("cp.async.commit_group;" ::: "memory")
#define CP_WAIT_GROUP_3() asm volatile("cp.async.wait_group 3;" ::: "memory")
#define SMEM_SWIZZLE_128B(b) ((b) ^ (((b) >> 3) & 0x70))

__device__ __forceinline__ void ldsm_x4(uint32_t* r, uint32_t addr) {
    asm volatile("ldmatrix.sync.aligned.m8n8.x4.shared.b16 {%0,%1,%2,%3}, [%4];"
                 : "=r"(r[0]), "=r"(r[1]), "=r"(r[2]), "=r"(r[3]) : "r"(addr));
}
__device__ __forceinline__ void mma16816_f16(float* d, const uint32_t* a, const uint32_t* b) {
    asm volatile(
        "mma.sync.aligned.m16n8k16.row.col.f32.f16.f16.f32 "
        "{%0,%1,%2,%3}, {%4,%5,%6,%7}, {%8,%9}, {%0,%1,%2,%3};"
        : "+f"(d[0]), "+f"(d[1]), "+f"(d[2]), "+f"(d[3])
        : "r"(a[0]), "r"(a[1]), "r"(a[2]), "r"(a[3]), "r"(b[0]), "r"(b[1]));
}

// ---------------------------------------------------------------------------
// Exact NVFP4 quantization math (bit-identical to fp32 reference)
// ---------------------------------------------------------------------------
__device__ __forceinline__ float q_e4m3(float x) {
    float s = (x > 0.f) ? 1.f : ((x < 0.f) ? -1.f : 0.f);
    float ax = fminf(fabsf(x), 448.0f);
    int e = -6;
    if (ax > 0.f) { e = ilogbf(ax); if (e < -6) e = -6; if (e > 8) e = 8; }
    float step  = __int_as_float((e + 127) << 23);
    float rstep = __int_as_float((127 - e) << 23);
    return s * (rintf(ax * rstep * 8.0f) * 0.125f * step);
}
__device__ __forceinline__ float q_e2m1(float x) {
    float s = (x > 0.f) ? 1.f : ((x < 0.f) ? -1.f : 0.f);
    float ax = fminf(fabsf(x), 6.0f);
    int e = 0;
    if (ax > 0.f) { e = ilogbf(ax); if (e < 0) e = 0; if (e > 2) e = 2; }
    float step  = __int_as_float((e + 127) << 23);
    float rstep = __int_as_float((127 - e) << 23);
    return s * (rintf(ax * rstep * 2.0f) * 0.5f * step);
}

// ---------------------------------------------------------------------------
// Fused prep kernel: quads [0, 4M) dequantize W -> fp16; quads [4M, 12M)
// convert x -> fp16. Both vectorized x4; one launch instead of two.
// ---------------------------------------------------------------------------
constexpr size_t W_QUADS = (size_t)O_DIM * I_DIM / 4;   // 4M
constexpr size_t X_QUADS = (size_t)T_DIM * I_DIM / 4;   // 8M
constexpr size_t PREP_QUADS = W_QUADS + X_QUADS;        // 12M

__global__ void prep_kernel(const float* __restrict__ x,
                            const float* __restrict__ w,
                            const float* __restrict__ pba,
                            const float* __restrict__ gam) {
    size_t q = (size_t)blockIdx.x * blockDim.x + threadIdx.x;
    if (q >= PREP_QUADS) return;
    if (q < W_QUADS) {
        size_t idx = q * 4;
        size_t o = idx >> 12;
        int i = (int)(idx & (I_DIM - 1));

        float gscale = __fdiv_rn(__ldg(gam), 2688.0f);           // /(6*448)
        float bf     = __fdiv_rn(__ldg(pba + o * (I_DIM / 16) + (i >> 4)), 6.0f);
        float bs     = q_e4m3(__fdiv_rn(bf, gscale)) * gscale;

        float4 wv = *reinterpret_cast<const float4*>(w + idx);
        float win[4] = {wv.x, wv.y, wv.z, wv.w};
        uint32_t hp[2];
#pragma unroll
        for (int j = 0; j < 2; j++) {
            float wd0 = 0.f, wd1 = 0.f;
            if (bs > 0.0f) {
                wd0 = q_e2m1(__fdiv_rn(win[2 * j + 0], fmaxf(bs, 1e-30f))) * bs;
                wd1 = q_e2m1(__fdiv_rn(win[2 * j + 1], fmaxf(bs, 1e-30f))) * bs;
            }
            __half2 hh;
            hh.x = __float2half_rn(wd0);
            hh.y = __float2half_rn(wd1);
            hp[j] = *reinterpret_cast<uint32_t*>(&hh);
        }
        *reinterpret_cast<uint2*>(g_Bh + idx) = make_uint2(hp[0], hp[1]);
    } else {
        size_t idx = (q - W_QUADS) * 4;
        float4 v = *reinterpret_cast<const float4*>(x + idx);
        __half2 h0, h1;
        h0.x = __float2half_rn(v.x);
        h0.y = __float2half_rn(v.y);
        h1.x = __float2half_rn(v.z);
        h1.y = __float2half_rn(v.w);
        *reinterpret_cast<uint2*>(g_Ah + idx) =
            make_uint2(*reinterpret_cast<uint32_t*>(&h0), *reinterpret_cast<uint32_t*>(&h1));
    }
}

// ===========================================================================
// PATH A: cg1 tcgen05 GEMM — R8 shape (BM=128 x BN=256, BK=64, 4 stages,
// 1024 CTAs / 7 waves) with warp-specialized producers + MMA warp.
// No __syncthreads / wait_group in the mainloop.
// ===========================================================================
constexpr int BM = 128;
constexpr int BN = 256;
constexpr int BK = 64;
constexpr int NCH = I_DIM / BK;                // 64 chunks
constexpr int NSTG = 4;
constexpr int A_BYTES = BM * 128;              // 16 KB
constexpr int B_BYTES = BN * 128;              // 32 KB
constexpr int STG_BYTES = A_BYTES + B_BYTES;   // 48 KB
constexpr int SM_TMEMPTR = 0;
constexpr int SM_FULL = 16;                    // 4 x 8B, count=256 (producers)
constexpr int SM_DONE = 48;                    // 4 x 8B, count=1   (commit)
constexpr int SM_TILES = 1024;
constexpr int SMEM_DYN = SM_TILES + NSTG * STG_BYTES;   // 197632 B
constexpr int GEMM_THREADS = 288;              // 256 producers + MMA warp (wid 8)

// idesc: D=F32, A=F16, B=F16, N=256, M=128
constexpr uint32_t IDESC =
    (1u << 4) | ((BN / 8) << 17) | ((BM / 16) << 24);

static constexpr uint64_t SMEM_DESC_BASE_SW128 =
    (uint64_t(2) << 61) | (uint64_t(1) << 46) | (uint64_t(64) << 32) | (uint64_t(1) << 16);
#define MAKE_SMEM_DESC(base_addr) \
    (SMEM_DESC_BASE_SW128 | ((uint64_t)((base_addr) >> 4) & 0x3FFF))

#if TCG_OK
__device__ __forceinline__ uint32_t elect_one_pred() {
    uint32_t pred;
    asm volatile(
        "{\n\t.reg .pred p;\n\telect.sync _|p, 0xFFFFFFFF;\n\tselp.b32 %0, 1, 0, p;\n\t}"
        : "=r"(pred));
    return pred;
}

#define MBARRIER_INIT(addr, count) \
    asm volatile("mbarrier.init.shared.b64 [%0], %1;" :: "r"((uint32_t)(addr)), "r"((uint32_t)(count)) : "memory")

#define MBARRIER_WAIT_PARITY(mbar_smem_addr, phase_parity) do { \
    uint32_t _mbar = (uint32_t)(mbar_smem_addr); \
    uint32_t _parity = (uint32_t)(phase_parity); \
    uint32_t _done; \
    asm volatile( \
        "{\n\t.reg .pred p;\n\t" \
        "mbarrier.try_wait.parity.acquire.cta.shared::cta.b64 p, [%1], %2;\n\t" \
        "selp.b32 %0, 1, 0, p;\n\t}" \
        : "=r"(_done) : "r"(_mbar), "r"(_parity) : "memory"); \
    if (!_done) { \
        asm volatile( \
            "{\n\t.reg .pred P1;\n\t" \
            "WAIT_LOOP_%=:\n\t" \
            "mbarrier.try_wait.parity.acquire.cta.shared::cta.b64 P1, [%0], %1, 0x989680;\n\t" \
            "@P1 bra.uni WAIT_DONE_%=;\n\t" \
            "bra.uni WAIT_LOOP_%=;\n\t" \
            "WAIT_DONE_%=:\n\t}" \
            :: "r"(_mbar), "r"(_parity) : "memory"); \
    } \
} while(0)

// Arrive on mbarrier when all prior cp.async of THIS thread have completed.
// .noinc: expected count pre-accounted at init (count = 256 producers).
#define CP_ASYNC_MBAR_ARRIVE(addr) \
    asm volatile("cp.async.mbarrier.arrive.noinc.shared::cta.b64 [%0];" \
        :: "r"((uint32_t)(addr)) : "memory")

#define TCGEN05_ALLOC(smem_result_addr, nCols) \
    asm volatile("tcgen05.alloc.cta_group::1.sync.aligned.shared::cta.b32 [%0], %1;" \
        :: "r"((uint32_t)(smem_result_addr)), "r"((uint32_t)(nCols)) : "memory")
#define TCGEN05_DEALLOC(tmem_addr, nCols) \
    asm volatile("tcgen05.dealloc.cta_group::1.sync.aligned.b32 %0, %1;" \
        :: "r"(tmem_addr), "r"((uint32_t)(nCols)))
#define TCGEN05_RELINQUISH_ALLOC_PERMIT() \
    asm volatile("tcgen05.relinquish_alloc_permit.cta_group::1.sync.aligned;")
#define TCGEN05_COMMIT(mbar_smem_addr) \
    asm volatile("tcgen05.commit.cta_group::1.mbarrier::arrive::one.shared::cluster.b64 [%0];" \
        :: "r"((uint32_t)(mbar_smem_addr)) : "memory")
#define TCGEN05_WAIT_LD() asm volatile("tcgen05.wait::ld.sync.aligned;" ::: "memory")
#define TCGEN05_FENCE_AFTER() asm volatile("tcgen05.fence::after_thread_sync;" ::: "memory")
#define FENCE_PROXY_ASYNC_SHARED_CTA() asm volatile("fence.proxy.async.shared::cta;" ::: "memory")

#define TCGEN05_LD_32X32B_X32(r, tmem_addr) \
    asm volatile( \
        "tcgen05.ld.sync.aligned.32x32b.x32.b32 " \
        "{%0, %1, %2, %3, %4, %5, %6, %7, " \
        " %8, %9, %10, %11, %12, %13, %14, %15, " \
        " %16, %17, %18, %19, %20, %21, %22, %23, " \
        " %24, %25, %26, %27, %28, %29, %30, %31}, [%32];" \
        : "=r"((r)[0]),  "=r"((r)[1]),  "=r"((r)[2]),  "=r"((r)[3]), \
          "=r"((r)[4]),  "=r"((r)[5]),  "=r"((r)[6]),  "=r"((r)[7]), \
          "=r"((r)[8]),  "=r"((r)[9]),  "=r"((r)[10]), "=r"((r)[11]), \
          "=r"((r)[12]), "=r"((r)[13]), "=r"((r)[14]), "=r"((r)[15]), \
          "=r"((r)[16]), "=r"((r)[17]), "=r"((r)[18]), "=r"((r)[19]), \
          "=r"((r)[20]), "=r"((r)[21]), "=r"((r)[22]), "=r"((r)[23]), \
          "=r"((r)[24]), "=r"((r)[25]), "=r"((r)[26]), "=r"((r)[27]), \
          "=r"((r)[28]), "=r"((r)[29]), "=r"((r)[30]), "=r"((r)[31]) \
        : "r"(tmem_addr))

__device__ __forceinline__ void mma_f16_ss(uint32_t d, uint64_t ad, uint64_t bd,
                                           uint32_t idesc, bool acc) {
    uint32_t en = acc ? 1u : 0u;
    asm volatile(
        "{\n\t.reg .pred p;\n\tsetp.ne.u32 p, %5, 0;\n\t"
        "tcgen05.mma.cta_group::1.kind::f16 [%0], %1, %2, %3, {%4, %4, %4, %4}, p;\n\t}"
        :: "r"(d), "l"(ad), "l"(bd), "r"(idesc), "r"(0u), "r"(en)
        : "memory");
}
#endif  // TCG_OK

__global__ void __launch_bounds__(GEMM_THREADS, 1)
nvfp4_gemm_tcgen05(float* __restrict__ out) {
#if TCG_OK
    extern __shared__ char smem[];
    const uint32_t sb = smem_to_u32(smem);
    const int tid = (int)threadIdx.x;
    const int wid = tid >> 5;
    const int lid = tid & 31;

    if (wid == 0) TCGEN05_ALLOC(sb + SM_TMEMPTR, 256);
    if (tid == 0) {
#pragma unroll
        for (int s = 0; s < NSTG; s++) {
            MBARRIER_INIT(sb + SM_FULL + 8 * s, 256);  // one arrive per producer
            MBARRIER_INIT(sb + SM_DONE + 8 * s, 1);    // tcgen05.commit arrival
        }
    }
    __syncthreads();
    uint32_t tmem;
    asm volatile("ld.shared.b32 %0, [%1];" : "=r"(tmem) : "r"(sb + SM_TMEMPTR));

    const size_t m0 = (size_t)blockIdx.y * BM;
    const size_t n0 = (size_t)blockIdx.x * BN;

    // ---------------- producers: tids 0..255, 4 A + 8 B slots of 16B ----------
    if (tid < 256) {
        uint32_t a_soff[4], b_soff[8];
        size_t a_goff[4], b_goff[8];
#pragma unroll
        for (int i = 0; i < 4; i++) {
            int idx = tid + i * 256;
            int r = idx >> 3, c16 = idx & 7;
            a_soff[i] = SMEM_SWIZZLE_128B((uint32_t)(r * 128 + c16 * 16));
            a_goff[i] = (m0 + r) * (size_t)I_DIM + (size_t)c16 * 8;
        }
#pragma unroll
        for (int i = 0; i < 8; i++) {
            int idx = tid + i * 256;
            int r = idx >> 3, c16 = idx & 7;
            b_soff[i] = (uint32_t)A_BYTES + SMEM_SWIZZLE_128B((uint32_t)(r * 128 + c16 * 16));
            b_goff[i] = (n0 + r) * (size_t)I_DIM + (size_t)c16 * 8;
        }
#pragma unroll 1
        for (int c = 0; c < NCH; c++) {
            int s = c & (NSTG - 1);
            if (c >= NSTG)                                 // stage reuse gate
                MBARRIER_WAIT_PARITY(sb + SM_DONE + 8 * s, ((c >> 2) - 1) & 1);
            uint32_t base = sb + SM_TILES + s * STG_BYTES;
            size_t kk = (size_t)c * BK;
#pragma unroll
            for (int i = 0; i < 4; i++) cp_async16(base + a_soff[i], g_Ah + a_goff[i] + kk);
#pragma unroll
            for (int i = 0; i < 8; i++) cp_async16(base + b_soff[i], g_Bh + b_goff[i] + kk);
            CP_ASYNC_MBAR_ARRIVE(sb + SM_FULL + 8 * s);
        }
    }

    // ---------------- MMA issuer: warp 8, one elected lane ----------------
    if (wid == 8) {
        if (elect_one_pred()) {
#pragma unroll 1
            for (int k = 0; k < NCH; k++) {
                int s = k & (NSTG - 1);
                MBARRIER_WAIT_PARITY(sb + SM_FULL + 8 * s, (k >> 2) & 1);
                FENCE_PROXY_ASYNC_SHARED_CTA();
                uint32_t base = sb + SM_TILES + s * STG_BYTES;
                uint64_t ad = MAKE_SMEM_DESC(base);
                uint64_t bd = MAKE_SMEM_DESC(base + A_BYTES);
                bool first = (k == 0);
#pragma unroll
                for (int j = 0; j < 4; j++)   // 4 x K=16 cover BK=64 (+2 = 32B)
                    mma_f16_ss(tmem, ad + j * 2, bd + j * 2, IDESC, !(first && j == 0));
                TCGEN05_COMMIT(sb + SM_DONE + 8 * s);
            }
        }
    }

    // ---------------- epilogue: wait final chunk's MMA, drain TMEM ----------
    MBARRIER_WAIT_PARITY(sb + SM_DONE + 8 * ((NCH - 1) & (NSTG - 1)),
                         ((NCH - 1) >> 2) & 1);
    TCGEN05_FENCE_AFTER();

    if (wid < 4) {
        size_t row = m0 + (size_t)(wid * 32 + lid);
        float* op = out + row * (size_t)O_DIM + n0;
#pragma unroll 1
        for (int cb = 0; cb < 8; cb++) {
            uint32_t r[32];
            TCGEN05_LD_32X32B_X32(r, tmem + cb * 32);
            TCGEN05_WAIT_LD();
#pragma unroll
            for (int q = 0; q < 8; q++) {
                float4 v;
                v.x = __uint_as_float(r[q * 4 + 0]);
                v.y = __uint_as_float(r[q * 4 + 1]);
                v.z = __uint_as_float(r[q * 4 + 2]);
                v.w = __uint_as_float(r[q * 4 + 3]);
                *reinterpret_cast<float4*>(op + cb * 32 + q * 4) = v;
            }
        }
    }

    __syncthreads();
    if (wid == 0) {
        TCGEN05_RELINQUISH_ALLOC_PERMIT();
        TCGEN05_DEALLOC(tmem, 256);
    }
#endif  // TCG_OK
}

// ===========================================================================
// PATH B: portable mma.sync fallback (fp16) — empty body in the live cubin
// ===========================================================================
constexpr int FBM = 128, FBN = 128, FBK = 64;
constexpr int FNCH = I_DIM / FBK;
constexpr int FSTG = 4;
constexpr int F_ABYTES = FBM * 128;
constexpr int F_STGB = F_ABYTES + FBN * 128;
constexpr int F_SMEM = FSTG * F_STGB;

__global__ void __launch_bounds__(256, 1)
nvfp4_gemm_mmasync(float* __restrict__ out) {
#if !TCG_OK
    extern __shared__ char smem[];
    const uint32_t sb = smem_to_u32(smem);
    const int tid = (int)threadIdx.x;
    const int wid = tid >> 5;
    const int lane = tid & 31;
    const int wm = wid & 1;
    const int wn = wid >> 1;

    const size_t m0 = (size_t)blockIdx.y * FBM;
    const size_t n0 = (size_t)blockIdx.x * FBN;

    uint32_t soff[8];
    size_t goff[8];
#pragma unroll
    for (int i = 0; i < 8; i++) {
        int idx = tid + i * 256;
        if (i < 4) {
            int r = idx >> 3, c16 = idx & 7;
            soff[i] = SMEM_SWIZZLE_128B((uint32_t)(r * 128 + c16 * 16));
            goff[i] = (m0 + r) * (size_t)I_DIM + (size_t)c16 * 8;
        } else {
            int idx2 = idx - 1024;
            int r = idx2 >> 3, c16 = idx2 & 7;
            soff[i] = (uint32_t)F_ABYTES + SMEM_SWIZZLE_128B((uint32_t)(r * 128 + c16 * 16));
            goff[i] = (n0 + r) * (size_t)I_DIM + (size_t)c16 * 8;
        }
    }

    auto load_chunk = [&](int c) {
        int s = c & (FSTG - 1);
        uint32_t base = sb + s * F_STGB;
        size_t kk = (size_t)c * FBK;
#pragma unroll
        for (int i = 0; i < 4; i++) cp_async16(base + soff[i], g_Ah + goff[i] + kk);
#pragma unroll
        for (int i = 4; i < 8; i++) cp_async16(base + soff[i], g_Bh + goff[i] + kk);
    };

    uint32_t arow128[4], axor[4];
    const uint32_t ahix = (uint32_t)((lane >> 4) * 16);
#pragma unroll
    for (int i = 0; i < 4; i++) {
        int row = wm * 64 + i * 16 + (lane & 7) + ((lane >> 3) & 1) * 8;
        arow128[i] = (uint32_t)(row * 128);
        axor[i] = (uint32_t)((row & 7) << 4);
    }
    uint32_t brow128[2], bxor[2];
    const uint32_t bhix = (uint32_t)(((lane >> 3) & 1) * 16);
#pragma unroll
    for (int jj = 0; jj < 2; jj++) {
        int row = wn * 32 + jj * 16 + (lane & 7) + ((lane >> 4) & 1) * 8;
        brow128[jj] = (uint32_t)(row * 128);
        bxor[jj] = (uint32_t)((row & 7) << 4);
    }

    float c[4][4][4];
#pragma unroll
    for (int i = 0; i < 4; i++)
#pragma unroll
        for (int j = 0; j < 4; j++)
#pragma unroll
            for (int r = 0; r < 4; r++) c[i][j][r] = 0.0f;

#pragma unroll 1
    for (int cch = 0; cch < FSTG; cch++) { load_chunk(cch); CP_COMMIT(); }

#pragma unroll 1
    for (int k = 0; k < FNCH; k++) {
        CP_WAIT_GROUP_3();
        __syncthreads();
        uint32_t Abase = sb + (uint32_t)((k & (FSTG - 1)) * F_STGB);
        uint32_t Bbase = Abase + F_ABYTES;
#pragma unroll
        for (int q = 0; q < 4; q++) {
            uint32_t qa = (uint32_t)(q * 32) + ahix;
            uint32_t qb = (uint32_t)(q * 32) + bhix;
            uint32_t a[4][4], b[2][4];
#pragma unroll
            for (int i = 0; i < 4; i++)
                ldsm_x4(a[i], Abase + arow128[i] + (qa ^ axor[i]));
#pragma unroll
            for (int jj = 0; jj < 2; jj++)
                ldsm_x4(b[jj], Bbase + brow128[jj] + (qb ^ bxor[jj]));
#pragma unroll
            for (int i = 0; i < 4; i++)
#pragma unroll
                for (int jj = 0; jj < 2; jj++) {
                    mma16816_f16(c[i][2 * jj + 0], a[i], &b[jj][0]);
                    mma16816_f16(c[i][2 * jj + 1], a[i], &b[jj][2]);
                }
        }
        __syncthreads();
        if (k + FSTG < FNCH) load_chunk(k + FSTG);
        CP_COMMIT();
    }

    const size_t rbase = m0 + (size_t)(wm * 64) + (size_t)(lane >> 2);
    const size_t cbase = n0 + (size_t)(wn * 32) + (size_t)((lane & 3) * 2);
#pragma unroll
    for (int i = 0; i < 4; i++)
#pragma unroll
        for (int j = 0; j < 4; j++) {
            size_t row = rbase + (size_t)(i * 16);
            size_t col = cbase + (size_t)(j * 8);
            *reinterpret_cast<float2*>(out + row * O_DIM + col) =
                make_float2(c[i][j][0], c[i][j][1]);
            *reinterpret_cast<float2*>(out + (row + 8) * O_DIM + col) =
                make_float2(c[i][j][2], c[i][j][3]);
        }
#endif  // !TCG_OK
}

// ---------------------------------------------------------------------------
// Launch
// ---------------------------------------------------------------------------
extern "C" void kernel_launch(void* const* d_in, const int* in_sizes, int n_in,
                              void* d_out, int out_size) {
    const float* x   = (const float*)d_in[0];
    const float* w   = (const float*)d_in[1];
    const float* pba = (const float*)d_in[2];
    const float* gam = (const float*)d_in[3];
    float* out = (float*)d_out;

    cudaFuncSetAttribute(nvfp4_gemm_tcgen05,
                         cudaFuncAttributeMaxDynamicSharedMemorySize, SMEM_DYN);
    cudaFuncSetAttribute(nvfp4_gemm_mmasync,
                         cudaFuncAttributeMaxDynamicSharedMemorySize, F_SMEM);

    {
        prep_kernel<<<(unsigned)((PREP_QUADS + 255) / 256), 256>>>(x, w, pba, gam);
    }
    {
        dim3 grid(O_DIM / BN, T_DIM / BM, 1);   // (16, 64) = 1024 CTAs
        nvfp4_gemm_tcgen05<<<grid, GEMM_THREADS, SMEM_DYN>>>(out);
    }
    {
        dim3 grid(O_DIM / FBN, T_DIM / FBM, 1); // fallback (empty in live cubin)
        nvfp4_gemm_mmasync<<<grid, 256, F_SMEM>>>(out);
    }
}